// round 1
// baseline (speedup 1.0000x reference)
#include <cuda_runtime.h>
#include <cstdint>

// ---------------- scratch (static device globals; no allocation) ----------------
__device__ float g_h1[64 * 64 * 56 * 56];   // conv1 output, 51.4 MB
__device__ float g_pp[64 * 256 * 7];        // conv2 partial pooled sums per oh-group
__device__ float g_z[64 * 32];              // vMF samples

// =======================================================================
// conv1: x[64,6,224,224] (7x7, stride 4, pad 3) -> relu -> g_h1[64,64,56,56]
// Block: (ohg in [0,28): 2 oh rows) x (n in [0,64)). 224 threads.
// Thread tile: 2 oh x 4 ow x 4 oc.  smem: input tile + all weights.
// =======================================================================
__global__ __launch_bounds__(224) void conv1_kernel(const float* __restrict__ x,
                                                    const float* __restrict__ W1,
                                                    const float* __restrict__ b1) {
    extern __shared__ float sm[];
    float* sx = sm;                 // [6][11][232], col = iw+3
    float* sw = sm + 6 * 11 * 232;  // [294][64]  f=ci*49+kh*7+kw major, oc minor
    const int n = blockIdx.y, ohg = blockIdx.x;
    const int tid = threadIdx.x;

    for (int i = tid; i < 294 * 64; i += 224) {
        int oc = i & 63, f = i >> 6;
        sw[i] = W1[oc * 294 + f];
    }
    const int ih_base = 8 * ohg - 3;
    for (int i = tid; i < 6 * 11 * 232; i += 224) {
        int c = i % 232;
        int t = i / 232;
        int rr = t % 11, ci = t / 11;
        int ih = ih_base + rr, iw = c - 3;
        float v = 0.f;
        if (ih >= 0 && ih < 224 && iw >= 0 && iw < 224)
            v = x[((n * 6 + ci) * 224 + ih) * 224 + iw];
        sx[i] = v;
    }
    __syncthreads();

    const int ocg = tid & 15;    // oc base = ocg*4
    const int towg = tid >> 4;   // 0..13, ow base = towg*4

    float acc[2][4][4];
#pragma unroll
    for (int a = 0; a < 2; a++)
#pragma unroll
        for (int i = 0; i < 4; i++)
#pragma unroll
            for (int c = 0; c < 4; c++) acc[a][i][c] = 0.f;

#pragma unroll 1
    for (int ci = 0; ci < 6; ci++) {
#pragma unroll 1
        for (int kh = 0; kh < 7; kh++) {
            const float* xr0 = &sx[(ci * 11 + kh) * 232 + towg * 16];
            const float* xr1 = xr0 + 4 * 232;
            float xv0[20], xv1[20];
#pragma unroll
            for (int q = 0; q < 5; q++) {
                float4 t0 = *(const float4*)(xr0 + q * 4);
                xv0[q * 4 + 0] = t0.x; xv0[q * 4 + 1] = t0.y;
                xv0[q * 4 + 2] = t0.z; xv0[q * 4 + 3] = t0.w;
                float4 t1 = *(const float4*)(xr1 + q * 4);
                xv1[q * 4 + 0] = t1.x; xv1[q * 4 + 1] = t1.y;
                xv1[q * 4 + 2] = t1.z; xv1[q * 4 + 3] = t1.w;
            }
            const float* wp = &sw[(ci * 49 + kh * 7) * 64 + ocg * 4];
#pragma unroll
            for (int kw = 0; kw < 7; kw++) {
                float4 w = *(const float4*)(wp + kw * 64);
#pragma unroll
                for (int i = 0; i < 4; i++) {
                    float a0 = xv0[i * 4 + kw], a1 = xv1[i * 4 + kw];
                    acc[0][i][0] = fmaf(a0, w.x, acc[0][i][0]);
                    acc[0][i][1] = fmaf(a0, w.y, acc[0][i][1]);
                    acc[0][i][2] = fmaf(a0, w.z, acc[0][i][2]);
                    acc[0][i][3] = fmaf(a0, w.w, acc[0][i][3]);
                    acc[1][i][0] = fmaf(a1, w.x, acc[1][i][0]);
                    acc[1][i][1] = fmaf(a1, w.y, acc[1][i][1]);
                    acc[1][i][2] = fmaf(a1, w.z, acc[1][i][2]);
                    acc[1][i][3] = fmaf(a1, w.w, acc[1][i][3]);
                }
            }
        }
    }

#pragma unroll
    for (int c = 0; c < 4; c++) {
        int oc = ocg * 4 + c;
        float bb = b1[oc];
#pragma unroll
        for (int ohh = 0; ohh < 2; ohh++) {
            int oh = 2 * ohg + ohh;
            float4 st;
            st.x = fmaxf(acc[ohh][0][c] + bb, 0.f);
            st.y = fmaxf(acc[ohh][1][c] + bb, 0.f);
            st.z = fmaxf(acc[ohh][2][c] + bb, 0.f);
            st.w = fmaxf(acc[ohh][3][c] + bb, 0.f);
            *(float4*)&g_h1[((n * 64 + oc) * 56 + oh) * 56 + towg * 4] = st;
        }
    }
}

// =======================================================================
// conv2: g_h1[64,64,56,56] (3x3, stride 2, pad 1) -> relu -> partial pooled
// Block: (ohg in [0,7): 4 oh) x (ocB in [0,4): 64 oc) x n. 224 threads.
// Thread tile: 4 oh x 1 ow x 8 oc. ci chunked by 16.
// Writes deterministic partial sums g_pp[(n*256+oc)*7 + ohg].
// =======================================================================
__global__ __launch_bounds__(224) void conv2_kernel(const float* __restrict__ W2,
                                                    const float* __restrict__ b2) {
    extern __shared__ float sm2[];
    float* sxc = sm2;                     // [16][9][60], col = iw+1
    float* sw2 = sm2 + 16 * 9 * 60;       // [16*9][64]  f=cil*9+kh*3+kw
    float* red = sw2 + 16 * 9 * 64;       // [28][64]
    const int ohg = blockIdx.x, ocB = blockIdx.y, n = blockIdx.z;
    const int tid = threadIdx.x;
    const int ocg = tid & 7;   // oc_local base = ocg*8
    const int tow = tid >> 3;  // 0..27

    float acc[4][8];
#pragma unroll
    for (int a = 0; a < 4; a++)
#pragma unroll
        for (int j = 0; j < 8; j++) acc[a][j] = 0.f;

    for (int c0 = 0; c0 < 64; c0 += 16) {
        __syncthreads();
        for (int i = tid; i < 16 * 9 * 60; i += 224) {
            int cc = i % 60;
            int t = i / 60;
            int rr = t % 9, cil = t / 9;
            int ih = 8 * ohg - 1 + rr, iw = cc - 1;
            float v = 0.f;
            if (ih >= 0 && ih < 56 && iw >= 0 && iw < 56)
                v = g_h1[((n * 64 + c0 + cil) * 56 + ih) * 56 + iw];
            sxc[i] = v;
        }
        for (int i = tid; i < 16 * 9 * 64; i += 224) {
            int oc = i & 63, f = i >> 6;
            int cil = f / 9, r = f % 9;
            sw2[i] = W2[(ocB * 64 + oc) * 576 + (c0 + cil) * 9 + r];
        }
        __syncthreads();
#pragma unroll 1
        for (int cil = 0; cil < 16; cil++) {
#pragma unroll
            for (int kh = 0; kh < 3; kh++) {
                float xv[4][3];
#pragma unroll
                for (int ohl = 0; ohl < 4; ohl++) {
                    const float* xr = &sxc[(cil * 9 + 2 * ohl + kh) * 60 + tow * 2];
                    xv[ohl][0] = xr[0]; xv[ohl][1] = xr[1]; xv[ohl][2] = xr[2];
                }
                const float* wp = &sw2[(cil * 9 + kh * 3) * 64 + ocg * 8];
#pragma unroll
                for (int kw = 0; kw < 3; kw++) {
                    float4 w0 = *(const float4*)(wp + kw * 64);
                    float4 w1 = *(const float4*)(wp + kw * 64 + 4);
#pragma unroll
                    for (int ohl = 0; ohl < 4; ohl++) {
                        float a = xv[ohl][kw];
                        acc[ohl][0] = fmaf(a, w0.x, acc[ohl][0]);
                        acc[ohl][1] = fmaf(a, w0.y, acc[ohl][1]);
                        acc[ohl][2] = fmaf(a, w0.z, acc[ohl][2]);
                        acc[ohl][3] = fmaf(a, w0.w, acc[ohl][3]);
                        acc[ohl][4] = fmaf(a, w1.x, acc[ohl][4]);
                        acc[ohl][5] = fmaf(a, w1.y, acc[ohl][5]);
                        acc[ohl][6] = fmaf(a, w1.z, acc[ohl][6]);
                        acc[ohl][7] = fmaf(a, w1.w, acc[ohl][7]);
                    }
                }
            }
        }
    }

    float part[8];
#pragma unroll
    for (int j = 0; j < 8; j++) {
        float bb = b2[ocB * 64 + ocg * 8 + j];
        float s = 0.f;
#pragma unroll
        for (int ohl = 0; ohl < 4; ohl++) s += fmaxf(acc[ohl][j] + bb, 0.f);
        part[j] = s;
    }
    __syncthreads();
#pragma unroll
    for (int j = 0; j < 8; j++) red[tow * 64 + ocg * 8 + j] = part[j];
    __syncthreads();
    if (tid < 64) {
        float s = 0.f;
        for (int t = 0; t < 28; t++) s += red[t * 64 + tid];
        g_pp[(n * 256 + ocB * 64 + tid) * 7 + ohg] = s;
    }
}

// =======================================================================
// fc: pooled -> h[512] -> mu (normalized, to out) + kappa (softplus+1, to out)
// =======================================================================
__global__ __launch_bounds__(512) void fc_kernel(const float* __restrict__ Wh,
                                                 const float* __restrict__ bh,
                                                 const float* __restrict__ Wmu,
                                                 const float* __restrict__ bmu,
                                                 const float* __restrict__ Wk,
                                                 const float* __restrict__ bk,
                                                 float* __restrict__ outp) {
    __shared__ float p[256];
    __shared__ float hrow[512];
    const int n = blockIdx.x;
    const int j = threadIdx.x;
    if (j < 256) {
        float s = 0.f;
#pragma unroll
        for (int g = 0; g < 7; g++) s += g_pp[(n * 256 + j) * 7 + g];
        p[j] = s * (1.0f / 784.0f);
    }
    __syncthreads();
    float s = bh[j];
    for (int k = 0; k < 256; k++) s = fmaf(p[k], Wh[k * 512 + j], s);
    hrow[j] = s;
    __syncthreads();
    if (j < 32) {
        float m = bmu[j];
        for (int k = 0; k < 512; k++) m = fmaf(hrow[k], Wmu[k * 32 + j], m);
        float ss = m * m;
#pragma unroll
        for (int o = 16; o > 0; o >>= 1) ss += __shfl_xor_sync(0xffffffffu, ss, o);
        float nrm = sqrtf(fmaxf(ss, 1e-24f));
        outp[448 + n * 32 + j] = m / nrm;
    } else if (j == 32) {
        float kk = bk[0];
        for (int k = 0; k < 512; k++) kk = fmaf(hrow[k], Wk[k], kk);
        float sp = fmaxf(kk, 0.f) + log1pf(expf(-fabsf(kk)));
        outp[2496 + n] = sp + 1.0f;
    }
}

// =======================================================================
// vMF sampling: JAX threefry (partitionable counters) for key(42)
// =======================================================================
__device__ __forceinline__ void tf2x32(uint32_t k0, uint32_t k1, uint32_t x0, uint32_t x1,
                                       uint32_t& o0, uint32_t& o1) {
    uint32_t k2 = k0 ^ k1 ^ 0x1BD11BDAu;
    x0 += k0; x1 += k1;
#define TF_RND(r) { x0 += x1; x1 = (x1 << (r)) | (x1 >> (32 - (r))); x1 ^= x0; }
    TF_RND(13) TF_RND(15) TF_RND(26) TF_RND(6)   x0 += k1; x1 += k2 + 1u;
    TF_RND(17) TF_RND(29) TF_RND(16) TF_RND(24)  x0 += k2; x1 += k0 + 2u;
    TF_RND(13) TF_RND(15) TF_RND(26) TF_RND(6)   x0 += k0; x1 += k1 + 3u;
    TF_RND(17) TF_RND(29) TF_RND(16) TF_RND(24)  x0 += k1; x1 += k2 + 4u;
    TF_RND(13) TF_RND(15) TF_RND(26) TF_RND(6)   x0 += k2; x1 += k0 + 5u;
#undef TF_RND
    o0 = x0; o1 = x1;
}

__device__ __forceinline__ float u01(uint32_t bits) {
    return __uint_as_float((bits >> 9) | 0x3f800000u) - 1.0f;
}

// XLA fp32 ErfInv (Giles polynomial), matches lax.erf_inv lowering
__device__ __forceinline__ float erfinvf_xla(float x) {
    float w = -log1pf(-x * x);
    float p;
    if (w < 5.f) {
        w -= 2.5f;
        p = 2.81022636e-08f;
        p = fmaf(p, w, 3.43273939e-07f);
        p = fmaf(p, w, -3.5233877e-06f);
        p = fmaf(p, w, -4.39150654e-06f);
        p = fmaf(p, w, 0.00021858087f);
        p = fmaf(p, w, -0.00125372503f);
        p = fmaf(p, w, -0.00417768164f);
        p = fmaf(p, w, 0.246640727f);
        p = fmaf(p, w, 1.50140941f);
    } else {
        w = sqrtf(w) - 3.f;
        p = -0.000200214257f;
        p = fmaf(p, w, 0.000100950558f);
        p = fmaf(p, w, 0.00134934322f);
        p = fmaf(p, w, -0.00367342844f);
        p = fmaf(p, w, 0.00573950773f);
        p = fmaf(p, w, -0.0076224613f);
        p = fmaf(p, w, 0.00943887047f);
        p = fmaf(p, w, 1.00167406f);
        p = fmaf(p, w, 2.83297682f);
    }
    return p * x;
}

__global__ void vmf_kernel(const float* __restrict__ outp) {
    const int b = threadIdx.x;  // 64 threads, one per batch row
    // split(key(42)) fold-like: k_w = blk(key,(0,0)), k_v = blk(key,(0,1))
    uint32_t kw0, kw1, kv0, kv1;
    tf2x32(0u, 42u, 0u, 0u, kw0, kw1);
    tf2x32(0u, 42u, 0u, 1u, kv0, kv1);

    float kap = outp[2496 + b];
    float w = 0.f;
    bool accq = false;
    for (int i = 0; i < 10; i++) {
        uint32_t c0, c1, d0, d1, y0, y1;
        tf2x32(kw0, kw1, 0u, (uint32_t)(2 * i), c0, c1);       // fold_in(k_w, 2i)
        tf2x32(kw0, kw1, 0u, (uint32_t)(2 * i + 1), d0, d1);   // fold_in(k_w, 2i+1)
        tf2x32(c0, c1, 0u, (uint32_t)b, y0, y1);               // partitionable draw
        float uc = u01(y0 ^ y1);
        float wc = __fadd_rn(__fmul_rn(2.f, uc), -1.f);
        tf2x32(d0, d1, 0u, (uint32_t)b, y0, y1);
        float ur = u01(y0 ^ y1);
        float logr = logf(ur + 1e-40f);
        float om = fmaxf(__fadd_rn(1.f, -__fmul_rn(wc, wc)), 1e-40f);
        float logp = __fadd_rn(__fmul_rn(kap, wc), __fmul_rn(14.5f, logf(om)));
        bool newly = (logr + kap <= logp) && !accq;
        if (newly) w = wc;
        accq = accq || newly;
    }
    w = fminf(fmaxf(w, -1.f), 1.f);

    float v[31];
    float ss = 0.f;
    const float lo = -0.99999994f;  // nextafterf(-1,0)
#pragma unroll
    for (int j = 0; j < 31; j++) {
        uint32_t e = (uint32_t)(b * 31 + j);
        uint32_t y0, y1;
        tf2x32(kv0, kv1, 0u, e, y0, y1);
        float f = u01(y0 ^ y1);
        float uu = fmaxf(lo, __fadd_rn(__fmul_rn(f, 2.0f), lo));  // (1-lo) rounds to 2.0f
        v[j] = 1.41421356f * erfinvf_xla(uu);
        ss += v[j] * v[j];
    }
    float nv = sqrtf(fmaxf(ss, 1e-24f));
    float st = sqrtf(fmaxf(1.f - w * w, 1e-40f));
    float zt[32];
#pragma unroll
    for (int j = 0; j < 31; j++) zt[j] = st * (v[j] / nv);
    zt[31] = w;

    float uh[32];
    float ssu = 0.f;
#pragma unroll
    for (int j = 0; j < 32; j++) {
        float mm = outp[448 + b * 32 + j];
        uh[j] = ((j == 31) ? 1.f : 0.f) - mm;
        ssu += uh[j] * uh[j];
    }
    float nu = sqrtf(fmaxf(ssu, 1e-24f));
    float dot = 0.f;
#pragma unroll
    for (int j = 0; j < 32; j++) {
        uh[j] /= nu;
        dot += zt[j] * uh[j];
    }
#pragma unroll
    for (int j = 0; j < 32; j++) g_z[b * 32 + j] = zt[j] - 2.f * dot * uh[j];
}

// =======================================================================
// MLP head: z -> 512 -> 512 -> 32 -> 7
// =======================================================================
__global__ __launch_bounds__(512) void mlp_kernel(const float* __restrict__ M1,
                                                  const float* __restrict__ bM1,
                                                  const float* __restrict__ M2,
                                                  const float* __restrict__ bM2,
                                                  const float* __restrict__ M3,
                                                  const float* __restrict__ bM3,
                                                  const float* __restrict__ M4,
                                                  const float* __restrict__ bM4,
                                                  float* __restrict__ outp) {
    __shared__ float z[32], y1s[512], y2s[512], y3s[32];
    const int n = blockIdx.x, j = threadIdx.x;
    if (j < 32) z[j] = g_z[n * 32 + j];
    __syncthreads();
    float s = bM1[j];
#pragma unroll
    for (int k = 0; k < 32; k++) s = fmaf(z[k], M1[k * 512 + j], s);
    y1s[j] = fmaxf(s, 0.f);
    __syncthreads();
    s = bM2[j];
    for (int k = 0; k < 512; k++) s = fmaf(y1s[k], M2[k * 512 + j], s);
    y2s[j] = fmaxf(s, 0.f);
    __syncthreads();
    if (j < 32) {
        s = bM3[j];
        for (int k = 0; k < 512; k++) s = fmaf(y2s[k], M3[k * 32 + j], s);
        y3s[j] = fmaxf(s, 0.f);
    }
    __syncthreads();
    if (j < 7) {
        s = bM4[j];
#pragma unroll
        for (int k = 0; k < 32; k++) s = fmaf(y3s[k], M4[k * 7 + j], s);
        outp[n * 7 + j] = s;
    }
}

// =======================================================================
extern "C" void kernel_launch(void* const* d_in, const int* in_sizes, int n_in,
                              void* d_out, int out_size) {
    (void)in_sizes; (void)n_in; (void)out_size;
    const float* x   = (const float*)d_in[0];
    const float* W1  = (const float*)d_in[1];
    const float* b1  = (const float*)d_in[2];
    const float* W2  = (const float*)d_in[3];
    const float* b2  = (const float*)d_in[4];
    const float* Wh  = (const float*)d_in[5];
    const float* bh  = (const float*)d_in[6];
    const float* Wmu = (const float*)d_in[7];
    const float* bmu = (const float*)d_in[8];
    const float* Wk  = (const float*)d_in[9];
    const float* bk  = (const float*)d_in[10];
    const float* M1  = (const float*)d_in[11];
    const float* bM1 = (const float*)d_in[12];
    const float* M2  = (const float*)d_in[13];
    const float* bM2 = (const float*)d_in[14];
    const float* M3  = (const float*)d_in[15];
    const float* bM3 = (const float*)d_in[16];
    const float* M4  = (const float*)d_in[17];
    const float* bM4 = (const float*)d_in[18];
    float* outp = (float*)d_out;

    const size_t s1 = (size_t)(6 * 11 * 232 + 294 * 64) * sizeof(float);        // 136512 B
    const size_t s2 = (size_t)(16 * 9 * 60 + 16 * 9 * 64 + 28 * 64) * sizeof(float);  // 78592 B
    cudaFuncSetAttribute(conv1_kernel, cudaFuncAttributeMaxDynamicSharedMemorySize, (int)s1);
    cudaFuncSetAttribute(conv2_kernel, cudaFuncAttributeMaxDynamicSharedMemorySize, (int)s2);

    conv1_kernel<<<dim3(28, 64), 224, s1>>>(x, W1, b1);
    conv2_kernel<<<dim3(7, 4, 64), 224, s2>>>(W2, b2);
    fc_kernel<<<64, 512>>>(Wh, bh, Wmu, bmu, Wk, bk, outp);
    vmf_kernel<<<1, 64>>>(outp);
    mlp_kernel<<<64, 512>>>(M1, bM1, M2, bM2, M3, bM3, M4, bM4, outp);
}

// round 2
// speedup vs baseline: 1.3069x; 1.3069x over previous
#include <cuda_runtime.h>
#include <cstdint>

// ---------------- scratch (static device globals; no allocation) ----------------
__device__ float g_h1[64 * 64 * 56 * 56];   // conv1 output
__device__ float g_pp[64 * 256 * 7];        // conv2 partial pooled sums per oh-group
__device__ float g_z[64 * 32];              // vMF samples

// =======================================================================
// conv1: x[64,6,224,224] (7x7 s4 p3) -> relu -> g_h1[64,64,56,56]
// grid(14,64), block 224, 2 blocks/SM.
// Block tile: 4 oh x 56 ow x 64 oc. Thread tile: 2oh x 4ow x 8oc.
// smem per ci-chunk(3): x[3][19][232] + w[3][49][64] = 90.5KB
// =======================================================================
__global__ __launch_bounds__(224, 2) void conv1_kernel(const float* __restrict__ x,
                                                       const float* __restrict__ W1,
                                                       const float* __restrict__ b1) {
    extern __shared__ float sm[];
    float* sx = sm;                  // [3][19][232], col = iw+3
    float* sw = sm + 3 * 19 * 232;   // [3][49][64]
    const int n = blockIdx.y, ohg = blockIdx.x;
    const int tid = threadIdx.x;
    const int ocg = tid & 7;          // oc = ocg*8 + j
    const int tow = (tid >> 3) % 14;  // ow = tow*4 + owl
    const int hgrp = tid / 112;       // oh_local = 2*hgrp + ohl
    const int ih_base = 16 * ohg - 3;

    float acc[2][4][8];
#pragma unroll
    for (int a = 0; a < 2; a++)
#pragma unroll
        for (int i = 0; i < 4; i++)
#pragma unroll
            for (int c = 0; c < 8; c++) acc[a][i][c] = 0.f;

    for (int c0 = 0; c0 < 6; c0 += 3) {
        __syncthreads();
        for (int i = tid; i < 3 * 19 * 232; i += 224) {
            int col = i % 232;
            int t = i / 232;
            int rr = t % 19, cil = t / 19;
            int ih = ih_base + rr, iw = col - 3;
            float v = 0.f;
            if (ih >= 0 && ih < 224 && iw >= 0 && iw < 224)
                v = x[((n * 6 + c0 + cil) * 224 + ih) * 224 + iw];
            sx[i] = v;
        }
        for (int i = tid; i < 3 * 49 * 64; i += 224) {
            int oc = i & 63, f = i >> 6;
            int cil = f / 49, r = f % 49;
            sw[i] = W1[oc * 294 + (c0 + cil) * 49 + r];
        }
        __syncthreads();

#pragma unroll 1
        for (int cil = 0; cil < 3; cil++) {
#pragma unroll 1
            for (int kh = 0; kh < 7; kh++) {
                const float* xp0 = &sx[(cil * 19 + 8 * hgrp + kh) * 232 + tow * 16];
                const float* xp1 = xp0 + 4 * 232;
                float xv[2][20];
#pragma unroll
                for (int q = 0; q < 5; q++) {
                    float4 t0 = *(const float4*)(xp0 + 4 * q);
                    xv[0][4 * q + 0] = t0.x; xv[0][4 * q + 1] = t0.y;
                    xv[0][4 * q + 2] = t0.z; xv[0][4 * q + 3] = t0.w;
                    float4 t1 = *(const float4*)(xp1 + 4 * q);
                    xv[1][4 * q + 0] = t1.x; xv[1][4 * q + 1] = t1.y;
                    xv[1][4 * q + 2] = t1.z; xv[1][4 * q + 3] = t1.w;
                }
                const float* wp = &sw[(cil * 49 + kh * 7) * 64 + ocg * 8];
#pragma unroll
                for (int kw = 0; kw < 7; kw++) {
                    float4 w0 = *(const float4*)(wp + kw * 64);
                    float4 w1 = *(const float4*)(wp + kw * 64 + 4);
#pragma unroll
                    for (int ohl = 0; ohl < 2; ohl++) {
#pragma unroll
                        for (int owl = 0; owl < 4; owl++) {
                            float a = xv[ohl][4 * owl + kw];
                            acc[ohl][owl][0] = fmaf(a, w0.x, acc[ohl][owl][0]);
                            acc[ohl][owl][1] = fmaf(a, w0.y, acc[ohl][owl][1]);
                            acc[ohl][owl][2] = fmaf(a, w0.z, acc[ohl][owl][2]);
                            acc[ohl][owl][3] = fmaf(a, w0.w, acc[ohl][owl][3]);
                            acc[ohl][owl][4] = fmaf(a, w1.x, acc[ohl][owl][4]);
                            acc[ohl][owl][5] = fmaf(a, w1.y, acc[ohl][owl][5]);
                            acc[ohl][owl][6] = fmaf(a, w1.z, acc[ohl][owl][6]);
                            acc[ohl][owl][7] = fmaf(a, w1.w, acc[ohl][owl][7]);
                        }
                    }
                }
            }
        }
    }

#pragma unroll
    for (int j = 0; j < 8; j++) {
        int oc = ocg * 8 + j;
        float bb = b1[oc];
#pragma unroll
        for (int ohl = 0; ohl < 2; ohl++) {
            int oh = 4 * ohg + 2 * hgrp + ohl;
            float4 st;
            st.x = fmaxf(acc[ohl][0][j] + bb, 0.f);
            st.y = fmaxf(acc[ohl][1][j] + bb, 0.f);
            st.z = fmaxf(acc[ohl][2][j] + bb, 0.f);
            st.w = fmaxf(acc[ohl][3][j] + bb, 0.f);
            *(float4*)&g_h1[((n * 64 + oc) * 56 + oh) * 56 + tow * 4] = st;
        }
    }
}

// =======================================================================
// conv2: g_h1 (3x3 s2 p1) -> relu -> pooled partials
// grid(7,2,64): ohg(4 oh rows), ocB(128 oc), n. block 224, 2 blocks/SM.
// Thread tile: 2oh x 4ow x 8oc. ci chunk 8. smem 61.3KB.
// =======================================================================
__global__ __launch_bounds__(224, 2) void conv2_kernel(const float* __restrict__ W2,
                                                       const float* __restrict__ b2) {
    extern __shared__ float sm2[];
    float* sxc = sm2;                     // [8][9][60], col = iw+1
    float* sw2 = sm2 + 8 * 9 * 60;        // [8][9][128]
    float* red = sw2 + 8 * 9 * 128;       // [14][128]
    const int ohg = blockIdx.x, ocB = blockIdx.y, n = blockIdx.z;
    const int tid = threadIdx.x;
    const int ocg = tid & 15;         // oc_local = ocg*8 + j
    const int tow = (tid >> 4) % 7;   // ow = tow*4 + owl
    const int hgrp = tid / 112;       // oh_local = 2*hgrp + ohl

    float acc[2][4][8];
#pragma unroll
    for (int a = 0; a < 2; a++)
#pragma unroll
        for (int i = 0; i < 4; i++)
#pragma unroll
            for (int c = 0; c < 8; c++) acc[a][i][c] = 0.f;

    for (int c0 = 0; c0 < 64; c0 += 8) {
        __syncthreads();
        for (int i = tid; i < 8 * 9 * 60; i += 224) {
            int col = i % 60;
            int t = i / 60;
            int rr = t % 9, cil = t / 9;
            int ih = 8 * ohg - 1 + rr, iw = col - 1;
            float v = 0.f;
            if (ih >= 0 && ih < 56 && iw >= 0 && iw < 56)
                v = g_h1[((n * 64 + c0 + cil) * 56 + ih) * 56 + iw];
            sxc[i] = v;
        }
        for (int i = tid; i < 8 * 9 * 128; i += 224) {
            int oc = i & 127, f = i >> 7;
            int cil = f / 9, r = f % 9;
            sw2[i] = W2[(ocB * 128 + oc) * 576 + (c0 + cil) * 9 + r];
        }
        __syncthreads();

#pragma unroll 1
        for (int cil = 0; cil < 8; cil++) {
#pragma unroll
            for (int kh = 0; kh < 3; kh++) {
                const float* xpA = &sxc[(cil * 9 + 4 * hgrp + kh) * 60 + tow * 8];
                const float* xpB = xpA + 2 * 60;
                float xr[2][9];
                {
                    float4 a0 = *(const float4*)xpA;
                    float4 a1 = *(const float4*)(xpA + 4);
                    xr[0][0] = a0.x; xr[0][1] = a0.y; xr[0][2] = a0.z; xr[0][3] = a0.w;
                    xr[0][4] = a1.x; xr[0][5] = a1.y; xr[0][6] = a1.z; xr[0][7] = a1.w;
                    xr[0][8] = xpA[8];
                    float4 c0v = *(const float4*)xpB;
                    float4 c1v = *(const float4*)(xpB + 4);
                    xr[1][0] = c0v.x; xr[1][1] = c0v.y; xr[1][2] = c0v.z; xr[1][3] = c0v.w;
                    xr[1][4] = c1v.x; xr[1][5] = c1v.y; xr[1][6] = c1v.z; xr[1][7] = c1v.w;
                    xr[1][8] = xpB[8];
                }
                const float* wp = &sw2[(cil * 9 + kh * 3) * 128 + ocg * 8];
#pragma unroll
                for (int kw = 0; kw < 3; kw++) {
                    float4 w0 = *(const float4*)(wp + kw * 128);
                    float4 w1 = *(const float4*)(wp + kw * 128 + 4);
#pragma unroll
                    for (int ohl = 0; ohl < 2; ohl++) {
#pragma unroll
                        for (int owl = 0; owl < 4; owl++) {
                            float a = xr[ohl][2 * owl + kw];
                            acc[ohl][owl][0] = fmaf(a, w0.x, acc[ohl][owl][0]);
                            acc[ohl][owl][1] = fmaf(a, w0.y, acc[ohl][owl][1]);
                            acc[ohl][owl][2] = fmaf(a, w0.z, acc[ohl][owl][2]);
                            acc[ohl][owl][3] = fmaf(a, w0.w, acc[ohl][owl][3]);
                            acc[ohl][owl][4] = fmaf(a, w1.x, acc[ohl][owl][4]);
                            acc[ohl][owl][5] = fmaf(a, w1.y, acc[ohl][owl][5]);
                            acc[ohl][owl][6] = fmaf(a, w1.z, acc[ohl][owl][6]);
                            acc[ohl][owl][7] = fmaf(a, w1.w, acc[ohl][owl][7]);
                        }
                    }
                }
            }
        }
    }

    float part[8];
#pragma unroll
    for (int j = 0; j < 8; j++) {
        float bb = b2[ocB * 128 + ocg * 8 + j];
        float s = 0.f;
#pragma unroll
        for (int ohl = 0; ohl < 2; ohl++)
#pragma unroll
            for (int owl = 0; owl < 4; owl++) s += fmaxf(acc[ohl][owl][j] + bb, 0.f);
        part[j] = s;
    }
    __syncthreads();
    {
        int g = hgrp * 7 + tow;
#pragma unroll
        for (int j = 0; j < 8; j++) red[g * 128 + ocg * 8 + j] = part[j];
    }
    __syncthreads();
    if (tid < 128) {
        float s = 0.f;
#pragma unroll
        for (int g = 0; g < 14; g++) s += red[g * 128 + tid];
        g_pp[(n * 256 + ocB * 128 + tid) * 7 + ohg] = s;
    }
}

// =======================================================================
// fc: pooled -> h[512] -> mu (normalized) + kappa (softplus+1)
// =======================================================================
__global__ __launch_bounds__(512) void fc_kernel(const float* __restrict__ Wh,
                                                 const float* __restrict__ bh,
                                                 const float* __restrict__ Wmu,
                                                 const float* __restrict__ bmu,
                                                 const float* __restrict__ Wk,
                                                 const float* __restrict__ bk,
                                                 float* __restrict__ outp) {
    __shared__ float p[256];
    __shared__ float hrow[512];
    const int n = blockIdx.x;
    const int j = threadIdx.x;
    if (j < 256) {
        float s = 0.f;
#pragma unroll
        for (int g = 0; g < 7; g++) s += g_pp[(n * 256 + j) * 7 + g];
        p[j] = s * (1.0f / 784.0f);
    }
    __syncthreads();
    float s = bh[j];
    for (int k = 0; k < 256; k++) s = fmaf(p[k], Wh[k * 512 + j], s);
    hrow[j] = s;
    __syncthreads();
    if (j < 32) {
        float m = bmu[j];
        for (int k = 0; k < 512; k++) m = fmaf(hrow[k], Wmu[k * 32 + j], m);
        float ss = m * m;
#pragma unroll
        for (int o = 16; o > 0; o >>= 1) ss += __shfl_xor_sync(0xffffffffu, ss, o);
        float nrm = sqrtf(fmaxf(ss, 1e-24f));
        outp[448 + n * 32 + j] = m / nrm;
    } else if (j == 32) {
        float kk = bk[0];
        for (int k = 0; k < 512; k++) kk = fmaf(hrow[k], Wk[k], kk);
        float sp = fmaxf(kk, 0.f) + log1pf(expf(-fabsf(kk)));
        outp[2496 + n] = sp + 1.0f;
    }
}

// =======================================================================
// vMF sampling: JAX threefry (partitionable counters) for key(42).
// Parallelized: stage 1 over (i,b), stage 2 warp-per-b with shuffles.
// All candidate/accept math kept byte-identical to the passing version.
// =======================================================================
__device__ __forceinline__ void tf2x32(uint32_t k0, uint32_t k1, uint32_t x0, uint32_t x1,
                                       uint32_t& o0, uint32_t& o1) {
    uint32_t k2 = k0 ^ k1 ^ 0x1BD11BDAu;
    x0 += k0; x1 += k1;
#define TF_RND(r) { x0 += x1; x1 = (x1 << (r)) | (x1 >> (32 - (r))); x1 ^= x0; }
    TF_RND(13) TF_RND(15) TF_RND(26) TF_RND(6)   x0 += k1; x1 += k2 + 1u;
    TF_RND(17) TF_RND(29) TF_RND(16) TF_RND(24)  x0 += k2; x1 += k0 + 2u;
    TF_RND(13) TF_RND(15) TF_RND(26) TF_RND(6)   x0 += k0; x1 += k1 + 3u;
    TF_RND(17) TF_RND(29) TF_RND(16) TF_RND(24)  x0 += k1; x1 += k2 + 4u;
    TF_RND(13) TF_RND(15) TF_RND(26) TF_RND(6)   x0 += k2; x1 += k0 + 5u;
#undef TF_RND
    o0 = x0; o1 = x1;
}

__device__ __forceinline__ float u01(uint32_t bits) {
    return __uint_as_float((bits >> 9) | 0x3f800000u) - 1.0f;
}

__device__ __forceinline__ float erfinvf_xla(float x) {
    float w = -log1pf(-x * x);
    float p;
    if (w < 5.f) {
        w -= 2.5f;
        p = 2.81022636e-08f;
        p = fmaf(p, w, 3.43273939e-07f);
        p = fmaf(p, w, -3.5233877e-06f);
        p = fmaf(p, w, -4.39150654e-06f);
        p = fmaf(p, w, 0.00021858087f);
        p = fmaf(p, w, -0.00125372503f);
        p = fmaf(p, w, -0.00417768164f);
        p = fmaf(p, w, 0.246640727f);
        p = fmaf(p, w, 1.50140941f);
    } else {
        w = sqrtf(w) - 3.f;
        p = -0.000200214257f;
        p = fmaf(p, w, 0.000100950558f);
        p = fmaf(p, w, 0.00134934322f);
        p = fmaf(p, w, -0.00367342844f);
        p = fmaf(p, w, 0.00573950773f);
        p = fmaf(p, w, -0.0076224613f);
        p = fmaf(p, w, 0.00943887047f);
        p = fmaf(p, w, 1.00167406f);
        p = fmaf(p, w, 2.83297682f);
    }
    return p * x;
}

__global__ __launch_bounds__(1024) void vmf_kernel(float* __restrict__ outp) {
    __shared__ float swc[10][64];
    __shared__ int sok[10][64];
    const int tid = threadIdx.x;

    // ---- stage 1: one thread per (i, b) candidate ----
    if (tid < 640) {
        const int b = tid & 63;
        const int i = tid >> 6;
        uint32_t kw0, kw1;
        tf2x32(0u, 42u, 0u, 0u, kw0, kw1);
        float kap = outp[2496 + b];
        uint32_t c0, c1, d0, d1, y0, y1;
        tf2x32(kw0, kw1, 0u, (uint32_t)(2 * i), c0, c1);
        tf2x32(kw0, kw1, 0u, (uint32_t)(2 * i + 1), d0, d1);
        tf2x32(c0, c1, 0u, (uint32_t)b, y0, y1);
        float uc = u01(y0 ^ y1);
        float wc = __fadd_rn(__fmul_rn(2.f, uc), -1.f);
        tf2x32(d0, d1, 0u, (uint32_t)b, y0, y1);
        float ur = u01(y0 ^ y1);
        float logr = logf(ur + 1e-40f);
        float om = fmaxf(__fadd_rn(1.f, -__fmul_rn(wc, wc)), 1e-40f);
        float logp = __fadd_rn(__fmul_rn(kap, wc), __fmul_rn(14.5f, logf(om)));
        swc[i][b] = wc;
        sok[i][b] = (logr + kap <= logp) ? 1 : 0;
    }
    __syncthreads();

    // ---- stage 2: one warp per b (2 passes) ----
    const int warp = tid >> 5;
    const int j = tid & 31;
    uint32_t kv0, kv1;
    tf2x32(0u, 42u, 0u, 1u, kv0, kv1);

    for (int pass = 0; pass < 2; pass++) {
        const int b = warp + 32 * pass;
        // first accepted candidate (identical across lanes, broadcast reads)
        float w = 0.f;
        bool got = false;
#pragma unroll
        for (int i = 0; i < 10; i++) {
            if (sok[i][b] && !got) { w = swc[i][b]; got = true; }
        }
        w = fminf(fmaxf(w, -1.f), 1.f);

        float vj = 0.f, vsq = 0.f;
        const float lo = -0.99999994f;
        if (j < 31) {
            uint32_t y0, y1;
            tf2x32(kv0, kv1, 0u, (uint32_t)(b * 31 + j), y0, y1);
            float f = u01(y0 ^ y1);
            float uu = fmaxf(lo, __fadd_rn(__fmul_rn(f, 2.0f), lo));
            vj = 1.41421356f * erfinvf_xla(uu);
            vsq = vj * vj;
        }
        float ss = vsq;
#pragma unroll
        for (int o = 16; o > 0; o >>= 1) ss += __shfl_xor_sync(0xffffffffu, ss, o);
        float nv = sqrtf(fmaxf(ss, 1e-24f));
        float st = sqrtf(fmaxf(1.f - w * w, 1e-40f));
        float zt = (j < 31) ? st * (vj / nv) : w;

        float mm = outp[448 + b * 32 + j];
        float uh = ((j == 31) ? 1.f : 0.f) - mm;
        float ssu = uh * uh;
#pragma unroll
        for (int o = 16; o > 0; o >>= 1) ssu += __shfl_xor_sync(0xffffffffu, ssu, o);
        float nu = sqrtf(fmaxf(ssu, 1e-24f));
        float uhn = uh / nu;
        float dot = zt * uhn;
#pragma unroll
        for (int o = 16; o > 0; o >>= 1) dot += __shfl_xor_sync(0xffffffffu, dot, o);
        g_z[b * 32 + j] = zt - 2.f * dot * uhn;
    }
}

// =======================================================================
// MLP head: z -> 512 -> 512 -> 32 -> 7
// =======================================================================
__global__ __launch_bounds__(512) void mlp_kernel(const float* __restrict__ M1,
                                                  const float* __restrict__ bM1,
                                                  const float* __restrict__ M2,
                                                  const float* __restrict__ bM2,
                                                  const float* __restrict__ M3,
                                                  const float* __restrict__ bM3,
                                                  const float* __restrict__ M4,
                                                  const float* __restrict__ bM4,
                                                  float* __restrict__ outp) {
    __shared__ float z[32], y1s[512], y2s[512], y3s[32];
    const int n = blockIdx.x, j = threadIdx.x;
    if (j < 32) z[j] = g_z[n * 32 + j];
    __syncthreads();
    float s = bM1[j];
#pragma unroll
    for (int k = 0; k < 32; k++) s = fmaf(z[k], M1[k * 512 + j], s);
    y1s[j] = fmaxf(s, 0.f);
    __syncthreads();
    s = bM2[j];
    for (int k = 0; k < 512; k++) s = fmaf(y1s[k], M2[k * 512 + j], s);
    y2s[j] = fmaxf(s, 0.f);
    __syncthreads();
    if (j < 32) {
        s = bM3[j];
        for (int k = 0; k < 512; k++) s = fmaf(y2s[k], M3[k * 32 + j], s);
        y3s[j] = fmaxf(s, 0.f);
    }
    __syncthreads();
    if (j < 7) {
        s = bM4[j];
#pragma unroll
        for (int k = 0; k < 32; k++) s = fmaf(y3s[k], M4[k * 7 + j], s);
        outp[n * 7 + j] = s;
    }
}

// =======================================================================
extern "C" void kernel_launch(void* const* d_in, const int* in_sizes, int n_in,
                              void* d_out, int out_size) {
    (void)in_sizes; (void)n_in; (void)out_size;
    const float* x   = (const float*)d_in[0];
    const float* W1  = (const float*)d_in[1];
    const float* b1  = (const float*)d_in[2];
    const float* W2  = (const float*)d_in[3];
    const float* b2  = (const float*)d_in[4];
    const float* Wh  = (const float*)d_in[5];
    const float* bh  = (const float*)d_in[6];
    const float* Wmu = (const float*)d_in[7];
    const float* bmu = (const float*)d_in[8];
    const float* Wk  = (const float*)d_in[9];
    const float* bk  = (const float*)d_in[10];
    const float* M1  = (const float*)d_in[11];
    const float* bM1 = (const float*)d_in[12];
    const float* M2  = (const float*)d_in[13];
    const float* bM2 = (const float*)d_in[14];
    const float* M3  = (const float*)d_in[15];
    const float* bM3 = (const float*)d_in[16];
    const float* M4  = (const float*)d_in[17];
    const float* bM4 = (const float*)d_in[18];
    float* outp = (float*)d_out;

    const size_t s1 = (size_t)(3 * 19 * 232 + 3 * 49 * 64) * sizeof(float);            // 90528
    const size_t s2 = (size_t)(8 * 9 * 60 + 8 * 9 * 128 + 14 * 128) * sizeof(float);   // 61312
    cudaFuncSetAttribute(conv1_kernel, cudaFuncAttributeMaxDynamicSharedMemorySize, (int)s1);
    cudaFuncSetAttribute(conv2_kernel, cudaFuncAttributeMaxDynamicSharedMemorySize, (int)s2);

    conv1_kernel<<<dim3(14, 64), 224, s1>>>(x, W1, b1);
    conv2_kernel<<<dim3(7, 2, 64), 224, s2>>>(W2, b2);
    fc_kernel<<<64, 512>>>(Wh, bh, Wmu, bmu, Wk, bk, outp);
    vmf_kernel<<<1, 1024>>>(outp);
    mlp_kernel<<<64, 512>>>(M1, bM1, M2, bM2, M3, bM3, M4, bM4, outp);
}